// round 7
// baseline (speedup 1.0000x reference)
#include <cuda_runtime.h>
#include <cuda_bf16.h>

// Stencil gather: out[b][j][k][{center,up,right,down,left}] with edge-replicate.
// Input  [16,1024,1024] fp32 (64 MB read), output [16,1024,1024,5] (320 MB write).
//
// Round-6 design: L1-wavefront-minimal.
//  - R=4 row band per block: up/down neighbors come from registers
//    (6 row-loads per 4 rows instead of 12) -> halves L2 read traffic.
//  - No shared memory at all: horizontal neighbors via warp shuffle; warp- and
//    image-boundary lanes use a predicated clamped scalar LDG (clamped index
//    reproduces edge-replication exactly).
//  - 5 x STG.128 per thread per row, 80 contiguous bytes, fully coalesced.

#define W   1024
#define H   1024
#define NB  16
#define TPB 256   // 256 threads x float4 = one full row width
#define R   4     // rows per block

__global__ __launch_bounds__(TPB, 4)
void stencil5_kernel(const float* __restrict__ x, float* __restrict__ out)
{
    const int band = blockIdx.x;             // 0 .. NB*H/R - 1
    const int img  = band >> 8;              // H/R = 256 bands per image
    const int j0   = (band & 255) << 2;      // first center row of this band

    const int t    = threadIdx.x;
    const int lane = t & 31;
    const int k    = t << 2;                 // first pixel column this thread owns

    const float* xi = x + (size_t)img * (H * W);

    // Load R+2 rows of this thread's float4 column (halo rows clamped).
    float4 f[R + 2];
#pragma unroll
    for (int r = 0; r < R + 2; ++r) {
        int j = j0 + r - 1;
        j = j < 0 ? 0 : (j > H - 1 ? H - 1 : j);
        f[r] = *reinterpret_cast<const float4*>(xi + (size_t)j * W + k);
    }

    float* obase = out + ((size_t)img * H + j0) * (size_t)(W * 5) + (size_t)k * 5;

#pragma unroll
    for (int p = 0; p < R; ++p) {
        const float4 c = f[p + 1];   // center row
        const float4 u = f[p];       // row above (register, clamped)
        const float4 d = f[p + 2];   // row below (register, clamped)

        const float* row = xi + (size_t)(j0 + p) * W;

        // Horizontal neighbors of the float4 boundary pixels.
        float lv = __shfl_up_sync(0xFFFFFFFFu, c.w, 1);
        if (lane == 0)  lv = row[k > 0 ? k - 1 : 0];          // clamp => replicate
        float rv = __shfl_down_sync(0xFFFFFFFFu, c.x, 1);
        if (lane == 31) rv = row[k + 4 < W ? k + 4 : W - 1];  // clamp => replicate

        // 20 contiguous floats (pixels k..k+3, channels {c,u,r,d,l}) as 5xSTG.128.
        float4* o = reinterpret_cast<float4*>(obase + (size_t)p * (W * 5));
        o[0] = make_float4(c.x, u.x, c.y, d.x);   // c0 u0 r0 d0
        o[1] = make_float4(lv,  c.y, u.y, c.z);   // l0 c1 u1 r1
        o[2] = make_float4(d.y, c.x, c.z, u.z);   // d1 l1 c2 u2
        o[3] = make_float4(c.w, d.z, c.y, c.w);   // r2 d2 l2 c3
        o[4] = make_float4(u.w, rv,  d.w, c.z);   // u3 r3 d3 l3
    }
}

extern "C" void kernel_launch(void* const* d_in, const int* in_sizes, int n_in,
                              void* d_out, int out_size)
{
    const float* x = (const float*)d_in[0];
    float* out = (float*)d_out;
    (void)in_sizes; (void)n_in; (void)out_size;

    stencil5_kernel<<<NB * (H / R), TPB>>>(x, out);
}

// round 8
// speedup vs baseline: 1.4716x; 1.4716x over previous
#include <cuda_runtime.h>
#include <cuda_bf16.h>

// Stencil gather: out[b][j][k][{center,up,right,down,left}], edge-replicate.
// Input [16,1024,1024] fp32 (64 MB), output [16,1024,1024,5] (320 MB).
//
// Round-7: coalesced-store design.
//  - One pixel per lane; block = 256 threads = 256-px strip, walks 64 rows.
//  - Rolling registers (up/center/down) -> 1 row LDG per row, L2 reads /3.
//  - Warp-local smem transpose: STS at word 5*lane+ch (gcd(5,32)=1 =>
//    conflict-free), LDS at 32m+lane (conflict-free), then 5x STG.32 each
//    covering exactly one aligned 128B line (warp base is 640B-aligned).
//  - Horizontal neighbors via shuffle; warp-edge lanes use a clamped
//    1-lane L1-hit load (clamp == edge replication).

#define W    1024
#define H    1024
#define NB   16
#define TPB  256
#define RPB  64                 // rows walked per block
#define STRIPS (W / TPB)        // 4
#define BANDS  (H / RPB)        // 16

__global__ __launch_bounds__(TPB, 6)
void stencil5_kernel(const float* __restrict__ x, float* __restrict__ out)
{
    __shared__ float sbuf[TPB / 32][2][160];   // per-warp double buffer

    const int b     = blockIdx.x;              // img*64 + strip*16 + band
    const int band  =  b        & (BANDS - 1);
    const int strip = (b >> 4)  & (STRIPS - 1);
    const int img   =  b >> 6;

    const int t    = threadIdx.x;
    const int w    = t >> 5;
    const int lane = t & 31;
    const int k    = strip * TPB + t;          // this lane's pixel column
    const int kw   = strip * TPB + (w << 5);   // warp's base column
    const int j0   = band * RPB;

    const float* xim = x + (size_t)img * (H * W);
    const float* xc  = xim + k;                // column pointer (stride W)

    // Rolling registers: cu = row j-1 (clamped), cc = row j, cd = row j+1.
    float cu = xc[(size_t)(j0 == 0 ? 0 : j0 - 1) * W];
    float cc = xc[(size_t)j0 * W];
    float cd = xc[(size_t)(j0 + 1 < H ? j0 + 1 : H - 1) * W];

    float* op = out + (((size_t)img * H + j0) * W + kw) * 5;

#pragma unroll 4
    for (int j = j0; j < j0 + RPB; ++j) {
        // Prefetch row j+2 (consumed next iteration as 'down').
        const int jn = (j + 2 < H) ? j + 2 : H - 1;
        const float cnext = xc[(size_t)jn * W];

        // Horizontal neighbors of the center row.
        float lv = __shfl_up_sync(0xFFFFFFFFu, cc, 1);
        float rv = __shfl_down_sync(0xFFFFFFFFu, cc, 1);
        const float* row = xim + (size_t)j * W;
        if (lane == 0)  lv = (k == 0)     ? cc : row[k - 1];   // L1 hit
        if (lane == 31) rv = (k == W - 1) ? cc : row[k + 1];   // L1 hit

        // Warp-local transpose to output layout. Channel order: c,u,r,d,l.
        float* buf = sbuf[w][j & 1];
        const int s = 5 * lane;
        buf[s + 0] = cc;
        buf[s + 1] = cu;
        buf[s + 2] = rv;
        buf[s + 3] = cd;
        buf[s + 4] = lv;
        __syncwarp();

        // 5 coalesced 128B-line stores (warp base 640B-aligned).
#pragma unroll
        for (int m = 0; m < 5; ++m)
            op[(m << 5) + lane] = buf[(m << 5) + lane];

        // Roll.
        cu = cc; cc = cd; cd = cnext;
        op += (size_t)W * 5;
    }
}

extern "C" void kernel_launch(void* const* d_in, const int* in_sizes, int n_in,
                              void* d_out, int out_size)
{
    const float* x = (const float*)d_in[0];
    float* out = (float*)d_out;
    (void)in_sizes; (void)n_in; (void)out_size;

    stencil5_kernel<<<NB * STRIPS * BANDS, TPB>>>(x, out);
}

// round 9
// speedup vs baseline: 1.4844x; 1.0087x over previous
#include <cuda_runtime.h>
#include <cuda_bf16.h>

// Stencil gather: out[b][j][k][{center,up,right,down,left}], edge-replicate.
// Input [16,1024,1024] fp32 (64 MB), output [16,1024,1024,5] (320 MB).
//
// Round-8: single-wave residency.
//  - Identical datapath to round 7 (rolling rows -> 1 LDG/row; warp-local
//    conflict-free smem transpose; 5 coalesced 128B-line stores per row).
//  - __launch_bounds__(256, 8): n_conc = 148*8 = 1184 >= grid (1024), so the
//    whole grid runs as ONE wave. Round 7's (256,6) gave 888 concurrent ->
//    a 136-block second wave that couldn't saturate DRAM (dram_pct 62%).

#define W    1024
#define H    1024
#define NB   16
#define TPB  256
#define RPB  64                 // rows walked per block
#define STRIPS (W / TPB)        // 4
#define BANDS  (H / RPB)        // 16

__global__ __launch_bounds__(TPB, 8)
void stencil5_kernel(const float* __restrict__ x, float* __restrict__ out)
{
    __shared__ float sbuf[TPB / 32][2][160];   // per-warp double buffer

    const int b     = blockIdx.x;              // img*64 + strip*16 + band
    const int band  =  b        & (BANDS - 1);
    const int strip = (b >> 4)  & (STRIPS - 1);
    const int img   =  b >> 6;

    const int t    = threadIdx.x;
    const int w    = t >> 5;
    const int lane = t & 31;
    const int k    = strip * TPB + t;          // this lane's pixel column
    const int kw   = strip * TPB + (w << 5);   // warp's base column
    const int j0   = band * RPB;

    const float* xim = x + (size_t)img * (H * W);
    const float* xc  = xim + k;                // column pointer (stride W)

    // Rolling registers: cu = row j-1 (clamped), cc = row j, cd = row j+1.
    float cu = xc[(size_t)(j0 == 0 ? 0 : j0 - 1) * W];
    float cc = xc[(size_t)j0 * W];
    float cd = xc[(size_t)(j0 + 1 < H ? j0 + 1 : H - 1) * W];

    float* op = out + (((size_t)img * H + j0) * W + kw) * 5;

#pragma unroll 4
    for (int j = j0; j < j0 + RPB; ++j) {
        // Prefetch row j+2 (consumed next iteration as 'down').
        const int jn = (j + 2 < H) ? j + 2 : H - 1;
        const float cnext = xc[(size_t)jn * W];

        // Horizontal neighbors of the center row.
        float lv = __shfl_up_sync(0xFFFFFFFFu, cc, 1);
        float rv = __shfl_down_sync(0xFFFFFFFFu, cc, 1);
        const float* row = xim + (size_t)j * W;
        if (lane == 0)  lv = (k == 0)     ? cc : row[k - 1];   // L1 hit
        if (lane == 31) rv = (k == W - 1) ? cc : row[k + 1];   // L1 hit

        // Warp-local transpose to output layout. Channel order: c,u,r,d,l.
        // STS at word 5*lane+ch: gcd(5,32)=1 -> conflict-free.
        float* buf = sbuf[w][j & 1];
        const int s = 5 * lane;
        buf[s + 0] = cc;
        buf[s + 1] = cu;
        buf[s + 2] = rv;
        buf[s + 3] = cd;
        buf[s + 4] = lv;
        __syncwarp();

        // 5 coalesced 128B-line stores (warp base 640B-aligned).
#pragma unroll
        for (int m = 0; m < 5; ++m)
            op[(m << 5) + lane] = buf[(m << 5) + lane];

        // Roll.
        cu = cc; cc = cd; cd = cnext;
        op += (size_t)W * 5;
    }
}

extern "C" void kernel_launch(void* const* d_in, const int* in_sizes, int n_in,
                              void* d_out, int out_size)
{
    const float* x = (const float*)d_in[0];
    float* out = (float*)d_out;
    (void)in_sizes; (void)n_in; (void)out_size;

    stencil5_kernel<<<NB * STRIPS * BANDS, TPB>>>(x, out);
}